// round 2
// baseline (speedup 1.0000x reference)
#include <cuda_runtime.h>
#include <cstdint>

#define BATCH 8192
#define OUTF  4096
#define INF   4096
#define PACKED_LEN 512

// ---------------- GEMM tiling ----------------
#define TM 128
#define TN 128
#define KS 128                       // int8 K elements per stage (128 B rows)
#define NK (INF / KS)                // 32 K-iterations
#define STAGES 3
#define THREADS 256

#define TILE_BYTES (TM * 128)        // 16 KB (one operand tile)
#define STAGE_BYTES (2 * TILE_BYTES) // 32 KB (A + B)
#define SMEM_DYN (STAGES * STAGE_BYTES + 1024)

// Scratch: unpacked +/-1 int8 (no cudaMalloc allowed -> __device__ globals)
__device__ __align__(16) int8_t g_A[(size_t)BATCH * INF];  // 32 MB
__device__ __align__(16) int8_t g_W[(size_t)OUTF * INF];   // 16 MB

// ---------------- helpers ----------------
__device__ __forceinline__ uint32_t smem_u32(const void* p) {
    return (uint32_t)__cvta_generic_to_shared(p);
}

__device__ __forceinline__ void cp_async16(uint32_t sdst, const void* gsrc) {
    asm volatile("cp.async.cg.shared.global [%0], [%1], 16;" :: "r"(sdst), "l"(gsrc));
}
__device__ __forceinline__ void cp_commit() {
    asm volatile("cp.async.commit_group;");
}
template <int N>
__device__ __forceinline__ void cp_wait() {
    asm volatile("cp.async.wait_group %0;" :: "n"(N));
}

__device__ __forceinline__ void ldsm_x4(uint32_t* r, uint32_t addr) {
    asm volatile("ldmatrix.sync.aligned.m8n8.x4.shared.b16 {%0,%1,%2,%3}, [%4];"
                 : "=r"(r[0]), "=r"(r[1]), "=r"(r[2]), "=r"(r[3]) : "r"(addr));
}

__device__ __forceinline__ void imma16832(int* c, const uint32_t* a,
                                          uint32_t b0, uint32_t b1) {
    asm volatile(
        "mma.sync.aligned.m16n8k32.row.col.s32.s8.s8.s32 "
        "{%0,%1,%2,%3}, {%4,%5,%6,%7}, {%8,%9}, {%0,%1,%2,%3};"
        : "+r"(c[0]), "+r"(c[1]), "+r"(c[2]), "+r"(c[3])
        : "r"(a[0]), "r"(a[1]), "r"(a[2]), "r"(a[3]), "r"(b0), "r"(b1));
}

// ---------------- Unpack: 8 bits (LSB-first) -> 8 int8 (+1 / -1) ----------------
// bit==1 -> 0x01, bit==0 -> 0xFF.  start at 0xFF, XOR 0xFE where bit set.
__device__ __forceinline__ uint2 unpack8(unsigned v) {
    uint2 r;
    r.x = 0xFFFFFFFFu ^ ((v & 1u) * 0xFEu)
                      ^ (((v >> 1) & 1u) * 0xFE00u)
                      ^ (((v >> 2) & 1u) * 0xFE0000u)
                      ^ (((v >> 3) & 1u) * 0xFE000000u);
    r.y = 0xFFFFFFFFu ^ (((v >> 4) & 1u) * 0xFEu)
                      ^ (((v >> 5) & 1u) * 0xFE00u)
                      ^ (((v >> 6) & 1u) * 0xFE0000u)
                      ^ (((v >> 7) & 1u) * 0xFE000000u);
    return r;
}

// two packed int32 per thread -> one 16B store
__global__ void unpack_A_kernel(const int* __restrict__ p, int n2) {
    int i = blockIdx.x * blockDim.x + threadIdx.x;
    if (i >= n2) return;
    uint2 lo = unpack8((unsigned)p[2 * i]);
    uint2 hi = unpack8((unsigned)p[2 * i + 1]);
    ((uint4*)g_A)[i] = make_uint4(lo.x, lo.y, hi.x, hi.y);
}
__global__ void unpack_W_kernel(const int* __restrict__ p, int n2) {
    int i = blockIdx.x * blockDim.x + threadIdx.x;
    if (i >= n2) return;
    uint2 lo = unpack8((unsigned)p[2 * i]);
    uint2 hi = unpack8((unsigned)p[2 * i + 1]);
    ((uint4*)g_W)[i] = make_uint4(lo.x, lo.y, hi.x, hi.y);
}

// ---------------- IMMA GEMM: out[b,o] = sum_k A[b,k]*W[o,k] + bias[o] ----------------
// CTA 128x128, 8 warps as 4(M) x 2(N): warp tile 32x64.
// smem tile: 128 rows x 128B, XOR-swizzled in 16B chunks: chunk' = chunk ^ (row&7).
__global__ __launch_bounds__(THREADS, 2)
void bitlinear_gemm(const float* __restrict__ bias, float* __restrict__ out) {
    extern __shared__ char smem_raw[];
    char* smem = (char*)(((uintptr_t)smem_raw + 1023) & ~(uintptr_t)1023);
    const uint32_t sbase = smem_u32(smem);

    const int tid  = threadIdx.x;
    const int wid  = tid >> 5;
    const int lane = tid & 31;
    const int warp_m = wid & 3;   // 0..3 -> 32 rows each
    const int warp_n = wid >> 2;  // 0..1 -> 64 cols each

    const int ntile = blockIdx.x & (OUTF / TN - 1);  // 0..31
    const int mtile = blockIdx.x >> 5;               // 0..63

    const int8_t* __restrict__ Ag0 = g_A + (size_t)(mtile * TM) * INF;
    const int8_t* __restrict__ Wg0 = g_W + (size_t)(ntile * TN) * INF;

    // per-thread cp.async assignment: 2048 chunks of 16B per stage
    // chunk id = tile*1024 + row*8 + c
    const int pf_tile = tid >> 7;          // 0..1 (first half threads -> A? no: see below)
    // We cover 2048 chunks with 256 threads x 8 iterations:
    //   cidx = tid + it*256; tile = cidx>>10; row = (cidx>>3)&127; c = cidx&7

    auto prefetch = [&](int kt) {
        const int s = kt % STAGES;
        const uint32_t sst = sbase + s * STAGE_BYTES;
#pragma unroll
        for (int it = 0; it < 8; ++it) {
            int cidx = tid + it * THREADS;          // 0..2047
            int tile = cidx >> 10;                  // 0 = A, 1 = B
            int row  = (cidx >> 3) & 127;
            int c    = cidx & 7;
            const int8_t* g = (tile ? Wg0 : Ag0) + (size_t)row * INF + kt * KS + c * 16;
            uint32_t sp = sst + tile * TILE_BYTES + row * 128 + ((c ^ (row & 7)) << 4);
            cp_async16(sp, g);
        }
        cp_commit();
    };
    (void)pf_tile;

    int c_acc[2][8][4];
#pragma unroll
    for (int mf = 0; mf < 2; ++mf)
#pragma unroll
        for (int nf = 0; nf < 8; ++nf)
#pragma unroll
            for (int k = 0; k < 4; ++k) c_acc[mf][nf][k] = 0;

#pragma unroll
    for (int s = 0; s < STAGES - 1; ++s) prefetch(s);

    // ldmatrix lane geometry
    const int j = lane >> 3;                       // tile index 0..3
    const int arow_in = (lane & 7) + ((j & 1) << 3);
    const int achk    = j >> 1;                    // 0/1 within kstep
    const int brow_in = (lane & 7) + ((j >> 1) << 3);
    const int bchk    = j & 1;

    for (int kt = 0; kt < NK; ++kt) {
        cp_wait<STAGES - 2>();
        __syncthreads();

        const uint32_t sa = sbase + (kt % STAGES) * STAGE_BYTES;
        const uint32_t sb = sa + TILE_BYTES;

#pragma unroll
        for (int ks = 0; ks < 4; ++ks) {
            uint32_t a[2][4];
#pragma unroll
            for (int mf = 0; mf < 2; ++mf) {
                int row = warp_m * 32 + mf * 16 + arow_in;
                int ch  = 2 * ks + achk;
                ldsm_x4(a[mf], sa + row * 128 + ((ch ^ (row & 7)) << 4));
            }
            uint32_t b[4][4];
#pragma unroll
            for (int nb = 0; nb < 4; ++nb) {
                int row = warp_n * 64 + nb * 16 + brow_in;
                int ch  = 2 * ks + bchk;
                ldsm_x4(b[nb], sb + row * 128 + ((ch ^ (row & 7)) << 4));
            }
#pragma unroll
            for (int mf = 0; mf < 2; ++mf)
#pragma unroll
                for (int nf = 0; nf < 8; ++nf)
                    imma16832(c_acc[mf][nf], a[mf],
                              b[nf >> 1][(nf & 1) * 2], b[nf >> 1][(nf & 1) * 2 + 1]);
        }

        __syncthreads();
        if (kt + STAGES - 1 < NK) prefetch(kt + STAGES - 1);
    }

    // ---------------- epilogue ----------------
    const int gid = lane >> 2;       // 0..7
    const int tig = lane & 3;        // 0..3
#pragma unroll
    for (int mf = 0; mf < 2; ++mf) {
        int r0 = mtile * TM + warp_m * 32 + mf * 16 + gid;
#pragma unroll
        for (int nf = 0; nf < 8; ++nf) {
            int col = ntile * TN + warp_n * 64 + nf * 8 + 2 * tig;
            float bx = __ldg(bias + col);
            float by = __ldg(bias + col + 1);
            float2 v0, v1;
            v0.x = (float)c_acc[mf][nf][0] + bx;
            v0.y = (float)c_acc[mf][nf][1] + by;
            v1.x = (float)c_acc[mf][nf][2] + bx;
            v1.y = (float)c_acc[mf][nf][3] + by;
            *(float2*)(void*)(out + (size_t)r0 * OUTF + col) = v0;
            *(float2*)(void*)(out + (size_t)(r0 + 8) * OUTF + col) = v1;
        }
    }
}

// ---------------- launch ----------------
extern "C" void kernel_launch(void* const* d_in, const int* in_sizes, int n_in,
                              void* d_out, int out_size) {
    const int*   inp  = (const int*)d_in[0];   // [8192, 512] int32 (low 8 bits)
    const int*   wp   = (const int*)d_in[1];   // [4096, 512] int32
    const float* bias = (const float*)d_in[2]; // [4096]
    float*       out  = (float*)d_out;         // [8192, 4096] fp32

    static int configured = 0;
    // cudaFuncSetAttribute is not a launch; safe pre-capture, but also
    // idempotent if it happens during capture it would fail -> call every time
    // is NOT capture-safe. Use attribute set unconditionally outside capture is
    // impossible to detect; cudaFuncSetAttribute IS graph-capture legal (host call).
    (void)configured;
    cudaFuncSetAttribute(bitlinear_gemm,
                         cudaFuncAttributeMaxDynamicSharedMemorySize, SMEM_DYN);

    const int nA2 = BATCH * PACKED_LEN / 2;  // 2097152 threads (2 words each)
    const int nW2 = OUTF * PACKED_LEN / 2;   // 1048576
    unpack_A_kernel<<<(nA2 + 255) / 256, 256>>>(inp, nA2);
    unpack_W_kernel<<<(nW2 + 255) / 256, 256>>>(wp, nW2);

    const int grid = (BATCH / TM) * (OUTF / TN);  // 2048
    bitlinear_gemm<<<grid, THREADS, SMEM_DYN>>>(bias, out);
}

// round 3
// speedup vs baseline: 1.0021x; 1.0021x over previous
#include <cuda_runtime.h>
#include <cstdint>

#define BATCH 8192
#define OUTF  4096
#define INF   4096
#define PACKED_LEN 512

// ---------------- GEMM tiling ----------------
#define TM 128
#define TN 128
#define KS 128                       // int8 K elements per stage (128 B rows)
#define NK (INF / KS)                // 32 K-iterations
#define STAGES 3
#define THREADS 256

#define TILE_BYTES (TM * 128)        // 16 KB (one operand tile)
#define STAGE_BYTES (2 * TILE_BYTES) // 32 KB (A + B)
#define SMEM_DYN (STAGES * STAGE_BYTES + 1024)

// Scratch: unpacked +/-1 int8 (no cudaMalloc allowed -> __device__ globals)
__device__ __align__(16) int8_t g_A[(size_t)BATCH * INF];  // 32 MB
__device__ __align__(16) int8_t g_W[(size_t)OUTF * INF];   // 16 MB

// ---------------- helpers ----------------
__device__ __forceinline__ uint32_t smem_u32(const void* p) {
    return (uint32_t)__cvta_generic_to_shared(p);
}

__device__ __forceinline__ void cp_async16(uint32_t sdst, const void* gsrc) {
    asm volatile("cp.async.cg.shared.global [%0], [%1], 16;" :: "r"(sdst), "l"(gsrc));
}
__device__ __forceinline__ void cp_commit() {
    asm volatile("cp.async.commit_group;");
}
template <int N>
__device__ __forceinline__ void cp_wait() {
    asm volatile("cp.async.wait_group %0;" :: "n"(N));
}

__device__ __forceinline__ void ldsm_x4(uint32_t* r, uint32_t addr) {
    asm volatile("ldmatrix.sync.aligned.m8n8.x4.shared.b16 {%0,%1,%2,%3}, [%4];"
                 : "=r"(r[0]), "=r"(r[1]), "=r"(r[2]), "=r"(r[3]) : "r"(addr));
}

__device__ __forceinline__ void imma16832(int* c, const uint32_t* a,
                                          uint32_t b0, uint32_t b1) {
    asm volatile(
        "mma.sync.aligned.m16n8k32.row.col.s32.s8.s8.s32 "
        "{%0,%1,%2,%3}, {%4,%5,%6,%7}, {%8,%9}, {%0,%1,%2,%3};"
        : "+r"(c[0]), "+r"(c[1]), "+r"(c[2]), "+r"(c[3])
        : "r"(a[0]), "r"(a[1]), "r"(a[2]), "r"(a[3]), "r"(b0), "r"(b1));
}

// ---------------- Unpack: 8 bits (LSB-first) -> 8 int8 (+1 / -1) ----------------
// bit==1 -> 0x01, bit==0 -> 0xFF.  start at 0xFF, XOR 0xFE where bit set.
__device__ __forceinline__ uint2 unpack8(unsigned v) {
    uint2 r;
    r.x = 0xFFFFFFFFu ^ ((v & 1u) * 0xFEu)
                      ^ (((v >> 1) & 1u) * 0xFE00u)
                      ^ (((v >> 2) & 1u) * 0xFE0000u)
                      ^ (((v >> 3) & 1u) * 0xFE000000u);
    r.y = 0xFFFFFFFFu ^ (((v >> 4) & 1u) * 0xFEu)
                      ^ (((v >> 5) & 1u) * 0xFE00u)
                      ^ (((v >> 6) & 1u) * 0xFE0000u)
                      ^ (((v >> 7) & 1u) * 0xFE000000u);
    return r;
}

// Fused unpack for A then W: i < nA2 -> A, else W. Two packed int32 -> 16 int8.
#define NA2 (BATCH * PACKED_LEN / 2)   // 2097152
#define NW2 (OUTF * PACKED_LEN / 2)    // 1048576
__global__ void unpack_all_kernel(const int* __restrict__ pa,
                                  const int* __restrict__ pw) {
    int i = blockIdx.x * blockDim.x + threadIdx.x;
    const int* src;
    uint4* dst;
    int idx;
    if (i < NA2) { src = pa; dst = (uint4*)g_A; idx = i; }
    else if (i < NA2 + NW2) { src = pw; dst = (uint4*)g_W; idx = i - NA2; }
    else return;
    uint2 lo = unpack8((unsigned)src[2 * idx]);
    uint2 hi = unpack8((unsigned)src[2 * idx + 1]);
    dst[idx] = make_uint4(lo.x, lo.y, hi.x, hi.y);
}

// ---------------- IMMA GEMM: out[b,o] = sum_k A[b,k]*W[o,k] + bias[o] ----------------
// CTA 128x128, 8 warps as 4(M) x 2(N): warp tile 32x64.
// smem tile: 128 rows x 128B, XOR-swizzled in 16B chunks: chunk' = chunk ^ (row&7).
__global__ __launch_bounds__(THREADS, 2)
void bitlinear_gemm(const float* __restrict__ bias, float* __restrict__ out) {
    extern __shared__ char smem_raw[];
    char* smem = (char*)(((uintptr_t)smem_raw + 1023) & ~(uintptr_t)1023);
    const uint32_t sbase = smem_u32(smem);

    const int tid  = threadIdx.x;
    const int wid  = tid >> 5;
    const int lane = tid & 31;
    const int warp_m = wid & 3;   // 0..3 -> 32 rows each
    const int warp_n = wid >> 2;  // 0..1 -> 64 cols each

    const int ntile = blockIdx.x & (OUTF / TN - 1);  // 0..31
    const int mtile = blockIdx.x >> 5;               // 0..63

    const int8_t* __restrict__ Ag0 = g_A + (size_t)(mtile * TM) * INF;
    const int8_t* __restrict__ Wg0 = g_W + (size_t)(ntile * TN) * INF;

    // cp.async assignment: 2048 chunks of 16B per stage.
    // cidx = tid + it*256; tile = cidx>>10 (0=A,1=B); row = (cidx>>3)&127; c = cidx&7
    auto prefetch = [&](int kt) {
        const int s = kt % STAGES;
        const uint32_t sst = sbase + s * STAGE_BYTES;
#pragma unroll
        for (int it = 0; it < 8; ++it) {
            int cidx = tid + it * THREADS;          // 0..2047
            int tile = cidx >> 10;                  // 0 = A, 1 = B
            int row  = (cidx >> 3) & 127;
            int c    = cidx & 7;
            const int8_t* g = (tile ? Wg0 : Ag0) + (size_t)row * INF + kt * KS + c * 16;
            uint32_t sp = sst + tile * TILE_BYTES + row * 128 + ((c ^ (row & 7)) << 4);
            cp_async16(sp, g);
        }
        cp_commit();
    };

    int c_acc[2][8][4];
#pragma unroll
    for (int mf = 0; mf < 2; ++mf)
#pragma unroll
        for (int nf = 0; nf < 8; ++nf)
#pragma unroll
            for (int k = 0; k < 4; ++k) c_acc[mf][nf][k] = 0;

    prefetch(0);
    prefetch(1);

    // ldmatrix lane geometry
    const int j = lane >> 3;                       // tile index 0..3
    const int arow_in = (lane & 7) + ((j & 1) << 3);
    const int achk    = j >> 1;                    // 0/1 within kstep
    const int brow_in = (lane & 7) + ((j >> 1) << 3);
    const int bchk    = j & 1;

    // precomputed per-thread smem row offsets (swizzle applied per-chunk below)
    for (int kt = 0; kt < NK; ++kt) {
        cp_wait<STAGES - 2>();
        __syncthreads();

        // Early prefetch: stage (kt+2)%3 == (kt-1)%3 is free after the barrier.
        if (kt + 2 < NK) prefetch(kt + 2);

        const uint32_t sa = sbase + (kt % STAGES) * STAGE_BYTES;
        const uint32_t sb = sa + TILE_BYTES;

        uint32_t a[2][2][4];   // [buf][mf][4]
        uint32_t b[2][4][4];   // [buf][nb][4]

        // load frags for ks = 0 into buf 0
#pragma unroll
        for (int mf = 0; mf < 2; ++mf) {
            int row = warp_m * 32 + mf * 16 + arow_in;
            ldsm_x4(a[0][mf], sa + row * 128 + (((0) * 2 + achk) ^ (row & 7)) * 16);
        }
#pragma unroll
        for (int nb = 0; nb < 4; ++nb) {
            int row = warp_n * 64 + nb * 16 + brow_in;
            ldsm_x4(b[0][nb], sb + row * 128 + (((0) * 2 + bchk) ^ (row & 7)) * 16);
        }

#pragma unroll
        for (int ks = 0; ks < 4; ++ks) {
            const int cur = ks & 1;
            const int nxt = cur ^ 1;
            if (ks < 3) {
                // prefetch next ks frags before issuing this ks's MMAs
#pragma unroll
                for (int mf = 0; mf < 2; ++mf) {
                    int row = warp_m * 32 + mf * 16 + arow_in;
                    int ch  = (ks + 1) * 2 + achk;
                    ldsm_x4(a[nxt][mf], sa + row * 128 + ((ch ^ (row & 7)) << 4));
                }
#pragma unroll
                for (int nb = 0; nb < 4; ++nb) {
                    int row = warp_n * 64 + nb * 16 + brow_in;
                    int ch  = (ks + 1) * 2 + bchk;
                    ldsm_x4(b[nxt][nb], sb + row * 128 + ((ch ^ (row & 7)) << 4));
                }
            }
#pragma unroll
            for (int mf = 0; mf < 2; ++mf)
#pragma unroll
                for (int nf = 0; nf < 8; ++nf)
                    imma16832(c_acc[mf][nf], a[cur][mf],
                              b[cur][nf >> 1][(nf & 1) * 2],
                              b[cur][nf >> 1][(nf & 1) * 2 + 1]);
        }
        // no trailing barrier: next iteration's top barrier protects stage reuse
    }

    // ---------------- epilogue ----------------
    const int gid = lane >> 2;       // 0..7
    const int tig = lane & 3;        // 0..3
#pragma unroll
    for (int mf = 0; mf < 2; ++mf) {
        int r0 = mtile * TM + warp_m * 32 + mf * 16 + gid;
#pragma unroll
        for (int nf = 0; nf < 8; ++nf) {
            int col = ntile * TN + warp_n * 64 + nf * 8 + 2 * tig;
            float bx = __ldg(bias + col);
            float by = __ldg(bias + col + 1);
            float2 v0, v1;
            v0.x = (float)c_acc[mf][nf][0] + bx;
            v0.y = (float)c_acc[mf][nf][1] + by;
            v1.x = (float)c_acc[mf][nf][2] + bx;
            v1.y = (float)c_acc[mf][nf][3] + by;
            *(float2*)(void*)(out + (size_t)r0 * OUTF + col) = v0;
            *(float2*)(void*)(out + (size_t)(r0 + 8) * OUTF + col) = v1;
        }
    }
}

// ---------------- launch ----------------
extern "C" void kernel_launch(void* const* d_in, const int* in_sizes, int n_in,
                              void* d_out, int out_size) {
    const int*   inp  = (const int*)d_in[0];   // [8192, 512] int32 (low 8 bits)
    const int*   wp   = (const int*)d_in[1];   // [4096, 512] int32
    const float* bias = (const float*)d_in[2]; // [4096]
    float*       out  = (float*)d_out;         // [8192, 4096] fp32

    cudaFuncSetAttribute(bitlinear_gemm,
                         cudaFuncAttributeMaxDynamicSharedMemorySize, SMEM_DYN);

    const int nTot = NA2 + NW2;  // 3145728
    unpack_all_kernel<<<(nTot + 255) / 256, 256>>>(inp, wp);

    const int grid = (BATCH / TM) * (OUTF / TN);  // 2048
    bitlinear_gemm<<<grid, THREADS, SMEM_DYN>>>(bias, out);
}

// round 4
// speedup vs baseline: 2.8265x; 2.8205x over previous
#include <cuda_runtime.h>
#include <cuda_fp16.h>
#include <cstdint>

#define BATCH 8192
#define OUTF  4096
#define INF   4096
#define PACKED_LEN 512

// ---------------- GEMM tiling ----------------
#define TM 128
#define TN 128
#define KS 128                       // fp8 K elements per stage (128 B rows)
#define NK (INF / KS)                // 32 K-iterations
#define STAGES 3
#define THREADS 256

#define TILE_BYTES (TM * 128)        // 16 KB (one operand tile)
#define STAGE_BYTES (2 * TILE_BYTES) // 32 KB (A + B)
#define SMEM_DYN (STAGES * STAGE_BYTES + 1024)

// Scratch: unpacked +/-1 e4m3 (no cudaMalloc allowed -> __device__ globals)
__device__ __align__(16) uint8_t g_A[(size_t)BATCH * INF];  // 32 MB
__device__ __align__(16) uint8_t g_W[(size_t)OUTF * INF];   // 16 MB

// ---------------- helpers ----------------
__device__ __forceinline__ uint32_t smem_u32(const void* p) {
    return (uint32_t)__cvta_generic_to_shared(p);
}

__device__ __forceinline__ void cp_async16(uint32_t sdst, const void* gsrc) {
    asm volatile("cp.async.cg.shared.global [%0], [%1], 16;" :: "r"(sdst), "l"(gsrc));
}
__device__ __forceinline__ void cp_commit() {
    asm volatile("cp.async.commit_group;");
}
template <int N>
__device__ __forceinline__ void cp_wait() {
    asm volatile("cp.async.wait_group %0;" :: "n"(N));
}

__device__ __forceinline__ void ldsm_x4(uint32_t* r, uint32_t addr) {
    asm volatile("ldmatrix.sync.aligned.m8n8.x4.shared.b16 {%0,%1,%2,%3}, [%4];"
                 : "=r"(r[0]), "=r"(r[1]), "=r"(r[2]), "=r"(r[3]) : "r"(addr));
}

// FP8 e4m3 x e4m3 -> f16 accumulator (exact: acc is always an even int <= 4096)
__device__ __forceinline__ void qmma_f16(uint32_t* c, const uint32_t* a,
                                         uint32_t b0, uint32_t b1) {
    asm volatile(
        "mma.sync.aligned.m16n8k32.row.col.f16.e4m3.e4m3.f16 "
        "{%0,%1}, {%2,%3,%4,%5}, {%6,%7}, {%0,%1};"
        : "+r"(c[0]), "+r"(c[1])
        : "r"(a[0]), "r"(a[1]), "r"(a[2]), "r"(a[3]), "r"(b0), "r"(b1));
}

// ---------------- Unpack: 8 bits (LSB-first) -> 8 e4m3 (+1 / -1) ----------------
// e4m3: +1.0 = 0x38, -1.0 = 0xB8. Start at 0xB8 (-1), clear sign bit where bit==1.
__device__ __forceinline__ uint2 unpack8(unsigned v) {
    uint2 r;
    r.x = 0xB8B8B8B8u ^ (((v >> 0) & 1u) << 7)
                      ^ (((v >> 1) & 1u) << 15)
                      ^ (((v >> 2) & 1u) << 23)
                      ^ (((v >> 3) & 1u) << 31);
    r.y = 0xB8B8B8B8u ^ (((v >> 4) & 1u) << 7)
                      ^ (((v >> 5) & 1u) << 15)
                      ^ (((v >> 6) & 1u) << 23)
                      ^ (((v >> 7) & 1u) << 31);
    return r;
}

// Fused unpack for A then W. Two packed int32 -> 16 fp8 bytes (one 16B store).
#define NA2 (BATCH * PACKED_LEN / 2)   // 2097152
#define NW2 (OUTF * PACKED_LEN / 2)    // 1048576
__global__ void unpack_all_kernel(const int* __restrict__ pa,
                                  const int* __restrict__ pw) {
    int i = blockIdx.x * blockDim.x + threadIdx.x;
    const int* src;
    uint4* dst;
    int idx;
    if (i < NA2) { src = pa; dst = (uint4*)g_A; idx = i; }
    else if (i < NA2 + NW2) { src = pw; dst = (uint4*)g_W; idx = i - NA2; }
    else return;
    uint2 lo = unpack8((unsigned)src[2 * idx]);
    uint2 hi = unpack8((unsigned)src[2 * idx + 1]);
    dst[idx] = make_uint4(lo.x, lo.y, hi.x, hi.y);
}

// ---------------- FP8 MMA GEMM: out[b,o] = sum_k A[b,k]*W[o,k] + bias[o] ----------------
// CTA 128x128, 8 warps as 4(M) x 2(N): warp tile 32x64.
// smem tile: 128 rows x 128B, XOR-swizzled in 16B chunks: chunk' = chunk ^ (row&7).
__global__ __launch_bounds__(THREADS, 2)
void bitlinear_gemm(const float* __restrict__ bias, float* __restrict__ out) {
    extern __shared__ char smem_raw[];
    char* smem = (char*)(((uintptr_t)smem_raw + 1023) & ~(uintptr_t)1023);
    const uint32_t sbase = smem_u32(smem);

    const int tid  = threadIdx.x;
    const int wid  = tid >> 5;
    const int lane = tid & 31;
    const int warp_m = wid & 3;   // 0..3 -> 32 rows each
    const int warp_n = wid >> 2;  // 0..1 -> 64 cols each

    const int ntile = blockIdx.x & (OUTF / TN - 1);  // 0..31
    const int mtile = blockIdx.x >> 5;               // 0..63

    const uint8_t* __restrict__ Ag0 = g_A + (size_t)(mtile * TM) * INF;
    const uint8_t* __restrict__ Wg0 = g_W + (size_t)(ntile * TN) * INF;

    // cp.async assignment: 2048 chunks of 16B per stage.
    auto prefetch = [&](int kt) {
        const int s = kt % STAGES;
        const uint32_t sst = sbase + s * STAGE_BYTES;
#pragma unroll
        for (int it = 0; it < 8; ++it) {
            int cidx = tid + it * THREADS;          // 0..2047
            int tile = cidx >> 10;                  // 0 = A, 1 = B
            int row  = (cidx >> 3) & 127;
            int c    = cidx & 7;
            const uint8_t* g = (tile ? Wg0 : Ag0) + (size_t)row * INF + kt * KS + c * 16;
            uint32_t sp = sst + tile * TILE_BYTES + row * 128 + ((c ^ (row & 7)) << 4);
            cp_async16(sp, g);
        }
        cp_commit();
    };

    // f16x2 accumulators: [mf][nf] -> 2 regs (row g / row g+8, cols {2t,2t+1})
    uint32_t c_acc[2][8][2];
#pragma unroll
    for (int mf = 0; mf < 2; ++mf)
#pragma unroll
        for (int nf = 0; nf < 8; ++nf) {
            c_acc[mf][nf][0] = 0u;
            c_acc[mf][nf][1] = 0u;
        }

    prefetch(0);
    prefetch(1);

    // ldmatrix lane geometry
    const int j = lane >> 3;                       // tile index 0..3
    const int arow_in = (lane & 7) + ((j & 1) << 3);
    const int achk    = j >> 1;                    // 0/1 within kstep
    const int brow_in = (lane & 7) + ((j >> 1) << 3);
    const int bchk    = j & 1;

    for (int kt = 0; kt < NK; ++kt) {
        cp_wait<STAGES - 2>();
        __syncthreads();

        // Early prefetch: stage (kt+2)%3 == (kt-1)%3 is free after the barrier.
        if (kt + 2 < NK) prefetch(kt + 2);

        const uint32_t sa = sbase + (kt % STAGES) * STAGE_BYTES;
        const uint32_t sb = sa + TILE_BYTES;

        uint32_t a[2][2][4];   // [buf][mf][4]
        uint32_t b[2][4][4];   // [buf][nb][4]

        // load frags for ks = 0 into buf 0
#pragma unroll
        for (int mf = 0; mf < 2; ++mf) {
            int row = warp_m * 32 + mf * 16 + arow_in;
            ldsm_x4(a[0][mf], sa + row * 128 + ((achk ^ (row & 7)) << 4));
        }
#pragma unroll
        for (int nb = 0; nb < 4; ++nb) {
            int row = warp_n * 64 + nb * 16 + brow_in;
            ldsm_x4(b[0][nb], sb + row * 128 + ((bchk ^ (row & 7)) << 4));
        }

#pragma unroll
        for (int ks = 0; ks < 4; ++ks) {
            const int cur = ks & 1;
            const int nxt = cur ^ 1;
            if (ks < 3) {
#pragma unroll
                for (int mf = 0; mf < 2; ++mf) {
                    int row = warp_m * 32 + mf * 16 + arow_in;
                    int ch  = (ks + 1) * 2 + achk;
                    ldsm_x4(a[nxt][mf], sa + row * 128 + ((ch ^ (row & 7)) << 4));
                }
#pragma unroll
                for (int nb = 0; nb < 4; ++nb) {
                    int row = warp_n * 64 + nb * 16 + brow_in;
                    int ch  = (ks + 1) * 2 + bchk;
                    ldsm_x4(b[nxt][nb], sb + row * 128 + ((ch ^ (row & 7)) << 4));
                }
            }
#pragma unroll
            for (int mf = 0; mf < 2; ++mf)
#pragma unroll
                for (int nf = 0; nf < 8; ++nf)
                    qmma_f16(c_acc[mf][nf], a[cur][mf],
                             b[cur][nf >> 1][(nf & 1) * 2],
                             b[cur][nf >> 1][(nf & 1) * 2 + 1]);
        }
    }

    // ---------------- epilogue ----------------
    const int gid = lane >> 2;       // 0..7
    const int tig = lane & 3;        // 0..3
#pragma unroll
    for (int mf = 0; mf < 2; ++mf) {
        int r0 = mtile * TM + warp_m * 32 + mf * 16 + gid;
#pragma unroll
        for (int nf = 0; nf < 8; ++nf) {
            int col = ntile * TN + warp_n * 64 + nf * 8 + 2 * tig;
            float bx = __ldg(bias + col);
            float by = __ldg(bias + col + 1);
            half2 h0 = *(half2*)&c_acc[mf][nf][0];   // row r0
            half2 h1 = *(half2*)&c_acc[mf][nf][1];   // row r0+8
            float2 f0 = __half22float2(h0);
            float2 f1 = __half22float2(h1);
            float2 v0, v1;
            v0.x = f0.x + bx;  v0.y = f0.y + by;
            v1.x = f1.x + bx;  v1.y = f1.y + by;
            *(float2*)(void*)(out + (size_t)r0 * OUTF + col) = v0;
            *(float2*)(void*)(out + (size_t)(r0 + 8) * OUTF + col) = v1;
        }
    }
}

// ---------------- launch ----------------
extern "C" void kernel_launch(void* const* d_in, const int* in_sizes, int n_in,
                              void* d_out, int out_size) {
    const int*   inp  = (const int*)d_in[0];   // [8192, 512] int32 (low 8 bits)
    const int*   wp   = (const int*)d_in[1];   // [4096, 512] int32
    const float* bias = (const float*)d_in[2]; // [4096]
    float*       out  = (float*)d_out;         // [8192, 4096] fp32

    cudaFuncSetAttribute(bitlinear_gemm,
                         cudaFuncAttributeMaxDynamicSharedMemorySize, SMEM_DYN);

    const int nTot = NA2 + NW2;  // 3145728
    unpack_all_kernel<<<(nTot + 255) / 256, 256>>>(inp, wp);

    const int grid = (BATCH / TM) * (OUTF / TN);  // 2048
    bitlinear_gemm<<<grid, THREADS, SMEM_DYN>>>(bias, out);
}

// round 5
// speedup vs baseline: 2.8418x; 1.0054x over previous
#include <cuda_runtime.h>
#include <cuda_fp16.h>
#include <cstdint>

#define BATCH 8192
#define OUTF  4096
#define INF   4096
#define PACKED_LEN 512

// ---------------- GEMM tiling ----------------
#define TM 128
#define TN 128
#define KS 128                       // fp8 K elements per stage (128 B rows)
#define NK (INF / KS)                // 32 K-iterations
#define STAGES 3
#define THREADS 256

#define TILE_BYTES (TM * 128)        // 16 KB (one operand tile)
#define STAGE_BYTES (2 * TILE_BYTES) // 32 KB (A + B)
#define SMEM_DYN (STAGES * STAGE_BYTES + 1024)

// Scratch: unpacked +/-1 e4m3 (no cudaMalloc allowed -> __device__ globals)
__device__ __align__(16) uint8_t g_A[(size_t)BATCH * INF];  // 32 MB
__device__ __align__(16) uint8_t g_W[(size_t)OUTF * INF];   // 16 MB

// ---------------- helpers ----------------
__device__ __forceinline__ uint32_t smem_u32(const void* p) {
    return (uint32_t)__cvta_generic_to_shared(p);
}

__device__ __forceinline__ void cp_async16(uint32_t sdst, const void* gsrc) {
    asm volatile("cp.async.cg.shared.global [%0], [%1], 16;" :: "r"(sdst), "l"(gsrc));
}
__device__ __forceinline__ void cp_commit() {
    asm volatile("cp.async.commit_group;");
}
template <int N>
__device__ __forceinline__ void cp_wait() {
    asm volatile("cp.async.wait_group %0;" :: "n"(N));
}

__device__ __forceinline__ void ldsm_x4(uint32_t* r, uint32_t addr) {
    asm volatile("ldmatrix.sync.aligned.m8n8.x4.shared.b16 {%0,%1,%2,%3}, [%4];"
                 : "=r"(r[0]), "=r"(r[1]), "=r"(r[2]), "=r"(r[3]) : "r"(addr));
}

// FP8 e4m3 x e4m3 -> f16 accumulator (exact: acc is always an even int <= 4096)
__device__ __forceinline__ void qmma_f16(uint32_t* c, const uint32_t* a,
                                         uint32_t b0, uint32_t b1) {
    asm volatile(
        "mma.sync.aligned.m16n8k32.row.col.f16.e4m3.e4m3.f16 "
        "{%0,%1}, {%2,%3,%4,%5}, {%6,%7}, {%0,%1};"
        : "+r"(c[0]), "+r"(c[1])
        : "r"(a[0]), "r"(a[1]), "r"(a[2]), "r"(a[3]), "r"(b0), "r"(b1));
}

// ---------------- Unpack: 8 bits (LSB-first) -> 8 e4m3 (+1 / -1) ----------------
// e4m3: +1.0 = 0x38, -1.0 = 0xB8. Start at 0xB8 (-1), clear sign bit where bit==1.
__device__ __forceinline__ uint2 unpack8(unsigned v) {
    uint2 r;
    r.x = 0xB8B8B8B8u ^ (((v >> 0) & 1u) << 7)
                      ^ (((v >> 1) & 1u) << 15)
                      ^ (((v >> 2) & 1u) << 23)
                      ^ (((v >> 3) & 1u) << 31);
    r.y = 0xB8B8B8B8u ^ (((v >> 4) & 1u) << 7)
                      ^ (((v >> 5) & 1u) << 15)
                      ^ (((v >> 6) & 1u) << 23)
                      ^ (((v >> 7) & 1u) << 31);
    return r;
}

// Fused unpack for A then W. Two packed int32 -> 16 fp8 bytes (one 16B store).
#define NA2 (BATCH * PACKED_LEN / 2)   // 2097152
#define NW2 (OUTF * PACKED_LEN / 2)    // 1048576
__global__ void unpack_all_kernel(const int* __restrict__ pa,
                                  const int* __restrict__ pw) {
    int i = blockIdx.x * blockDim.x + threadIdx.x;
    const int* src;
    uint4* dst;
    int idx;
    if (i < NA2) { src = pa; dst = (uint4*)g_A; idx = i; }
    else if (i < NA2 + NW2) { src = pw; dst = (uint4*)g_W; idx = i - NA2; }
    else return;
    uint2 lo = unpack8((unsigned)src[2 * idx]);
    uint2 hi = unpack8((unsigned)src[2 * idx + 1]);
    dst[idx] = make_uint4(lo.x, lo.y, hi.x, hi.y);
}

// ---------------- FP8 MMA GEMM: out[b,o] = sum_k A[b,k]*W[o,k] + bias[o] ----------------
// CTA 128x128, 8 warps as 4(M) x 2(N): warp tile 32x64.
// smem tile: 128 rows x 128B, XOR-swizzled in 16B chunks: chunk' = chunk ^ (row&7).
__global__ __launch_bounds__(THREADS, 2)
void bitlinear_gemm(const float* __restrict__ bias, float* __restrict__ out) {
    extern __shared__ char smem_raw[];
    char* smem = (char*)(((uintptr_t)smem_raw + 1023) & ~(uintptr_t)1023);
    const uint32_t sbase = smem_u32(smem);

    const int tid  = threadIdx.x;
    const int wid  = tid >> 5;
    const int lane = tid & 31;
    const int warp_m = wid & 3;   // 0..3 -> 32 rows each
    const int warp_n = wid >> 2;  // 0..1 -> 64 cols each

    const int ntile = blockIdx.x & (OUTF / TN - 1);  // 0..31
    const int mtile = blockIdx.x >> 5;               // 0..63

    const uint8_t* __restrict__ Ag0 = g_A + (size_t)(mtile * TM) * INF;
    const uint8_t* __restrict__ Wg0 = g_W + (size_t)(ntile * TN) * INF;

    // ---- prefetch geometry (all loop-invariant) ----
    // 2048 16B-chunks/stage; thread handles rows {it*32 + tid>>3}, chunk col tid&7,
    // for A (first 4 its) and B (last 4 its).
    const int tr = tid >> 3;    // 0..31
    const int tc = tid & 7;     // 0..7
    const uint8_t* pf_gA = Ag0 + (size_t)tr * INF + tc * 16;
    const uint8_t* pf_gW = Wg0 + (size_t)tr * INF + tc * 16;
    const uint32_t pf_sA = tr * 128 + ((tc ^ (tr & 7)) << 4);
    const uint32_t pf_sB = TILE_BYTES + pf_sA;

    auto prefetch = [&](int kt) {
        const uint32_t sst = sbase + (kt % STAGES) * STAGE_BYTES;
        const uint8_t* ga = pf_gA + kt * KS;
        const uint8_t* gw = pf_gW + kt * KS;
#pragma unroll
        for (int it = 0; it < 4; ++it)
            cp_async16(sst + pf_sA + it * (32 * 128), ga + (size_t)it * (32 * INF));
#pragma unroll
        for (int it = 0; it < 4; ++it)
            cp_async16(sst + pf_sB + it * (32 * 128), gw + (size_t)it * (32 * INF));
        cp_commit();
    };

    // ---- ldmatrix geometry (all loop-invariant): precompute 24 offsets ----
    const int j = lane >> 3;                       // 0..3
    const int arow_in = (lane & 7) + ((j & 1) << 3);
    const int achk    = j >> 1;
    const int brow_in = (lane & 7) + ((j >> 1) << 3);
    const int bchk    = j & 1;

    uint32_t offA[2][4];   // [mf][ks]
    uint32_t offB[4][4];   // [nb][ks]
#pragma unroll
    for (int mf = 0; mf < 2; ++mf) {
        int row = warp_m * 32 + mf * 16 + arow_in;
#pragma unroll
        for (int ks = 0; ks < 4; ++ks)
            offA[mf][ks] = row * 128 + (((ks * 2 + achk) ^ (row & 7)) << 4);
    }
#pragma unroll
    for (int nb = 0; nb < 4; ++nb) {
        int row = warp_n * 64 + nb * 16 + brow_in;
#pragma unroll
        for (int ks = 0; ks < 4; ++ks)
            offB[nb][ks] = TILE_BYTES + row * 128 + (((ks * 2 + bchk) ^ (row & 7)) << 4);
    }

    // f16x2 accumulators
    uint32_t c_acc[2][8][2];
#pragma unroll
    for (int mf = 0; mf < 2; ++mf)
#pragma unroll
        for (int nf = 0; nf < 8; ++nf) {
            c_acc[mf][nf][0] = 0u;
            c_acc[mf][nf][1] = 0u;
        }

    prefetch(0);
    prefetch(1);

    for (int kt = 0; kt < NK; ++kt) {
        cp_wait<STAGES - 2>();
        __syncthreads();

        // stage (kt+2)%3 == (kt-1)%3 is free after the barrier
        if (kt + 2 < NK) prefetch(kt + 2);

        const uint32_t sa = sbase + (kt % STAGES) * STAGE_BYTES;

#pragma unroll
        for (int ks = 0; ks < 4; ++ks) {
            uint32_t a[2][4], b[4][4];
#pragma unroll
            for (int mf = 0; mf < 2; ++mf) ldsm_x4(a[mf], sa + offA[mf][ks]);
#pragma unroll
            for (int nb = 0; nb < 4; ++nb) ldsm_x4(b[nb], sa + offB[nb][ks]);
#pragma unroll
            for (int mf = 0; mf < 2; ++mf)
#pragma unroll
                for (int nf = 0; nf < 8; ++nf)
                    qmma_f16(c_acc[mf][nf], a[mf],
                             b[nf >> 1][(nf & 1) * 2],
                             b[nf >> 1][(nf & 1) * 2 + 1]);
        }
    }

    // ---------------- epilogue ----------------
    const int gid = lane >> 2;       // 0..7
    const int tig = lane & 3;        // 0..3
#pragma unroll
    for (int mf = 0; mf < 2; ++mf) {
        int r0 = mtile * TM + warp_m * 32 + mf * 16 + gid;
#pragma unroll
        for (int nf = 0; nf < 8; ++nf) {
            int col = ntile * TN + warp_n * 64 + nf * 8 + 2 * tig;
            float bx = __ldg(bias + col);
            float by = __ldg(bias + col + 1);
            half2 h0 = *(half2*)&c_acc[mf][nf][0];   // row r0
            half2 h1 = *(half2*)&c_acc[mf][nf][1];   // row r0+8
            float2 f0 = __half22float2(h0);
            float2 f1 = __half22float2(h1);
            float2 v0, v1;
            v0.x = f0.x + bx;  v0.y = f0.y + by;
            v1.x = f1.x + bx;  v1.y = f1.y + by;
            *(float2*)(void*)(out + (size_t)r0 * OUTF + col) = v0;
            *(float2*)(void*)(out + (size_t)(r0 + 8) * OUTF + col) = v1;
        }
    }
}

// ---------------- launch ----------------
extern "C" void kernel_launch(void* const* d_in, const int* in_sizes, int n_in,
                              void* d_out, int out_size) {
    const int*   inp  = (const int*)d_in[0];   // [8192, 512] int32 (low 8 bits)
    const int*   wp   = (const int*)d_in[1];   // [4096, 512] int32
    const float* bias = (const float*)d_in[2]; // [4096]
    float*       out  = (float*)d_out;         // [8192, 4096] fp32

    cudaFuncSetAttribute(bitlinear_gemm,
                         cudaFuncAttributeMaxDynamicSharedMemorySize, SMEM_DYN);

    const int nTot = NA2 + NW2;  // 3145728
    unpack_all_kernel<<<(nTot + 255) / 256, 256>>>(inp, wp);

    const int grid = (BATCH / TM) * (OUTF / TN);  // 2048
    bitlinear_gemm<<<grid, THREADS, SMEM_DYN>>>(bias, out);
}

// round 6
// speedup vs baseline: 2.8748x; 1.0116x over previous
#include <cuda_runtime.h>
#include <cuda_fp16.h>
#include <cstdint>

#define BATCH 8192
#define OUTF  4096
#define INF   4096
#define PACKED_LEN 512

// ---------------- GEMM tiling ----------------
#define TM 128
#define TN 128
#define KS 128                       // fp8 K elements per stage (128 B rows)
#define NK (INF / KS)                // 32 K-iterations
#define STAGES 3
#define THREADS 256

#define TILE_BYTES (TM * 128)        // 16 KB (one operand tile)
#define STAGE_BYTES (2 * TILE_BYTES) // 32 KB (A + B)
#define SMEM_DYN (STAGES * STAGE_BYTES + 1024)

// Scratch: unpacked +/-1 e4m3 (no cudaMalloc allowed -> __device__ globals)
__device__ __align__(16) uint8_t g_A[(size_t)BATCH * INF];  // 32 MB
__device__ __align__(16) uint8_t g_W[(size_t)OUTF * INF];   // 16 MB

// ---------------- helpers ----------------
__device__ __forceinline__ uint32_t smem_u32(const void* p) {
    return (uint32_t)__cvta_generic_to_shared(p);
}

__device__ __forceinline__ void cp_async16(uint32_t sdst, const void* gsrc) {
    asm volatile("cp.async.cg.shared.global [%0], [%1], 16;" :: "r"(sdst), "l"(gsrc));
}
__device__ __forceinline__ void cp_commit() {
    asm volatile("cp.async.commit_group;");
}
template <int N>
__device__ __forceinline__ void cp_wait() {
    asm volatile("cp.async.wait_group %0;" :: "n"(N));
}

__device__ __forceinline__ void ldsm_x4(uint32_t* r, uint32_t addr) {
    asm volatile("ldmatrix.sync.aligned.m8n8.x4.shared.b16 {%0,%1,%2,%3}, [%4];"
                 : "=r"(r[0]), "=r"(r[1]), "=r"(r[2]), "=r"(r[3]) : "r"(addr));
}

// FP8 e4m3 x e4m3 -> f16 accumulator (exact: acc is always an even int <= 4096)
__device__ __forceinline__ void qmma_f16(uint32_t* c, const uint32_t* a,
                                         uint32_t b0, uint32_t b1) {
    asm volatile(
        "mma.sync.aligned.m16n8k32.row.col.f16.e4m3.e4m3.f16 "
        "{%0,%1}, {%2,%3,%4,%5}, {%6,%7}, {%0,%1};"
        : "+r"(c[0]), "+r"(c[1])
        : "r"(a[0]), "r"(a[1]), "r"(a[2]), "r"(a[3]), "r"(b0), "r"(b1));
}

// ---------------- Unpack: 8 bits (LSB-first) -> 8 e4m3 (+1 / -1) ----------------
__device__ __forceinline__ uint2 unpack8(unsigned v) {
    uint2 r;
    r.x = 0xB8B8B8B8u ^ (((v >> 0) & 1u) << 7)
                      ^ (((v >> 1) & 1u) << 15)
                      ^ (((v >> 2) & 1u) << 23)
                      ^ (((v >> 3) & 1u) << 31);
    r.y = 0xB8B8B8B8u ^ (((v >> 4) & 1u) << 7)
                      ^ (((v >> 5) & 1u) << 15)
                      ^ (((v >> 6) & 1u) << 23)
                      ^ (((v >> 7) & 1u) << 31);
    return r;
}

#define NA2 (BATCH * PACKED_LEN / 2)   // 2097152
#define NW2 (OUTF * PACKED_LEN / 2)    // 1048576
__global__ void unpack_all_kernel(const int* __restrict__ pa,
                                  const int* __restrict__ pw) {
    int i = blockIdx.x * blockDim.x + threadIdx.x;
    const int* src;
    uint4* dst;
    int idx;
    if (i < NA2) { src = pa; dst = (uint4*)g_A; idx = i; }
    else if (i < NA2 + NW2) { src = pw; dst = (uint4*)g_W; idx = i - NA2; }
    else return;
    uint2 lo = unpack8((unsigned)src[2 * idx]);
    uint2 hi = unpack8((unsigned)src[2 * idx + 1]);
    dst[idx] = make_uint4(lo.x, lo.y, hi.x, hi.y);
}

// ---------------- FP8 MMA GEMM ----------------
// Pipeline per kt (3 stages):
//   ks0: ldsm(kt,1)                 qmma(0)
//   ks1: ldsm(kt,2)                 qmma(1)
//   ks2: ldsm(kt,3)                 qmma(2)   cp_wait<1>  __syncthreads
//   ks3: prefetch(kt+3) ldsm(kt+1,0) qmma(3)
__global__ __launch_bounds__(THREADS, 2)
void bitlinear_gemm(const float* __restrict__ bias, float* __restrict__ out) {
    extern __shared__ char smem_raw[];
    char* smem = (char*)(((uintptr_t)smem_raw + 1023) & ~(uintptr_t)1023);
    const uint32_t sbase = smem_u32(smem);

    const int tid  = threadIdx.x;
    const int wid  = tid >> 5;
    const int lane = tid & 31;
    const int warp_m = wid & 3;
    const int warp_n = wid >> 2;

    const int ntile = blockIdx.x & (OUTF / TN - 1);
    const int mtile = blockIdx.x >> 5;

    const uint8_t* __restrict__ Ag0 = g_A + (size_t)(mtile * TM) * INF;
    const uint8_t* __restrict__ Wg0 = g_W + (size_t)(ntile * TN) * INF;

    const int tr = tid >> 3;
    const int tc = tid & 7;
    const uint8_t* pf_gA = Ag0 + (size_t)tr * INF + tc * 16;
    const uint8_t* pf_gW = Wg0 + (size_t)tr * INF + tc * 16;
    const uint32_t pf_sA = tr * 128 + ((tc ^ (tr & 7)) << 4);
    const uint32_t pf_sB = TILE_BYTES + pf_sA;

    auto prefetch = [&](int kt) {
        const uint32_t sst = sbase + (kt % STAGES) * STAGE_BYTES;
        const uint8_t* ga = pf_gA + kt * KS;
        const uint8_t* gw = pf_gW + kt * KS;
#pragma unroll
        for (int it = 0; it < 4; ++it)
            cp_async16(sst + pf_sA + it * (32 * 128), ga + (size_t)it * (32 * INF));
#pragma unroll
        for (int it = 0; it < 4; ++it)
            cp_async16(sst + pf_sB + it * (32 * 128), gw + (size_t)it * (32 * INF));
        cp_commit();
    };

    const int j = lane >> 3;
    const int arow_in = (lane & 7) + ((j & 1) << 3);
    const int achk    = j >> 1;
    const int brow_in = (lane & 7) + ((j >> 1) << 3);
    const int bchk    = j & 1;

    uint32_t offA[2][4];
    uint32_t offB[4][4];
#pragma unroll
    for (int mf = 0; mf < 2; ++mf) {
        int row = warp_m * 32 + mf * 16 + arow_in;
#pragma unroll
        for (int ks = 0; ks < 4; ++ks)
            offA[mf][ks] = row * 128 + (((ks * 2 + achk) ^ (row & 7)) << 4);
    }
#pragma unroll
    for (int nb = 0; nb < 4; ++nb) {
        int row = warp_n * 64 + nb * 16 + brow_in;
#pragma unroll
        for (int ks = 0; ks < 4; ++ks)
            offB[nb][ks] = TILE_BYTES + row * 128 + (((ks * 2 + bchk) ^ (row & 7)) << 4);
    }

    uint32_t c_acc[2][8][2];
#pragma unroll
    for (int mf = 0; mf < 2; ++mf)
#pragma unroll
        for (int nf = 0; nf < 8; ++nf) {
            c_acc[mf][nf][0] = 0u;
            c_acc[mf][nf][1] = 0u;
        }

    prefetch(0);
    prefetch(1);
    prefetch(2);
    cp_wait<2>();       // group 0 complete
    __syncthreads();    // visible CTA-wide

    uint32_t a[2][2][4];
    uint32_t b[2][4][4];

    {   // preload (kt=0, ks=0) into buf 0
        const uint32_t sa0 = sbase;
#pragma unroll
        for (int mf = 0; mf < 2; ++mf) ldsm_x4(a[0][mf], sa0 + offA[mf][0]);
#pragma unroll
        for (int nb = 0; nb < 4; ++nb) ldsm_x4(b[0][nb], sa0 + offB[nb][0]);
    }

    for (int kt = 0; kt < NK; ++kt) {
        const uint32_t sa = sbase + (kt % STAGES) * STAGE_BYTES;
        const uint32_t sn = sbase + ((kt + 1) % STAGES) * STAGE_BYTES;
        const bool last = (kt == NK - 1);

#pragma unroll
        for (int ks = 0; ks < 4; ++ks) {
            const int cur = ks & 1;
            const int nxt = cur ^ 1;

            if (ks < 3) {
#pragma unroll
                for (int mf = 0; mf < 2; ++mf) ldsm_x4(a[nxt][mf], sa + offA[mf][ks + 1]);
#pragma unroll
                for (int nb = 0; nb < 4; ++nb) ldsm_x4(b[nxt][nb], sa + offB[nb][ks + 1]);
            } else if (!last) {
                if (kt + 3 < NK) prefetch(kt + 3);
#pragma unroll
                for (int mf = 0; mf < 2; ++mf) ldsm_x4(a[nxt][mf], sn + offA[mf][0]);
#pragma unroll
                for (int nb = 0; nb < 4; ++nb) ldsm_x4(b[nxt][nb], sn + offB[nb][0]);
            }

#pragma unroll
            for (int mf = 0; mf < 2; ++mf)
#pragma unroll
                for (int nf = 0; nf < 8; ++nf)
                    qmma_f16(c_acc[mf][nf], a[cur][mf],
                             b[cur][nf >> 1][(nf & 1) * 2],
                             b[cur][nf >> 1][(nf & 1) * 2 + 1]);

            if (ks == 2 && !last) {
                cp_wait<1>();     // completes group kt+1 (outstanding {kt+1, kt+2})
                __syncthreads();  // visibility + closes reads of stage kt%3
            }
        }
    }

    // ---------------- epilogue ----------------
    const int gid = lane >> 2;
    const int tig = lane & 3;
#pragma unroll
    for (int mf = 0; mf < 2; ++mf) {
        int r0 = mtile * TM + warp_m * 32 + mf * 16 + gid;
#pragma unroll
        for (int nf = 0; nf < 8; ++nf) {
            int col = ntile * TN + warp_n * 64 + nf * 8 + 2 * tig;
            float bx = __ldg(bias + col);
            float by = __ldg(bias + col + 1);
            half2 h0 = *(half2*)&c_acc[mf][nf][0];
            half2 h1 = *(half2*)&c_acc[mf][nf][1];
            float2 f0 = __half22float2(h0);
            float2 f1 = __half22float2(h1);
            float2 v0, v1;
            v0.x = f0.x + bx;  v0.y = f0.y + by;
            v1.x = f1.x + bx;  v1.y = f1.y + by;
            *(float2*)(void*)(out + (size_t)r0 * OUTF + col) = v0;
            *(float2*)(void*)(out + (size_t)(r0 + 8) * OUTF + col) = v1;
        }
    }
}

// ---------------- launch ----------------
extern "C" void kernel_launch(void* const* d_in, const int* in_sizes, int n_in,
                              void* d_out, int out_size) {
    const int*   inp  = (const int*)d_in[0];
    const int*   wp   = (const int*)d_in[1];
    const float* bias = (const float*)d_in[2];
    float*       out  = (float*)d_out;

    cudaFuncSetAttribute(bitlinear_gemm,
                         cudaFuncAttributeMaxDynamicSharedMemorySize, SMEM_DYN);

    const int nTot = NA2 + NW2;
    unpack_all_kernel<<<(nTot + 255) / 256, 256>>>(inp, wp);

    const int grid = (BATCH / TM) * (OUTF / TN);
    bitlinear_gemm<<<grid, THREADS, SMEM_DYN>>>(bias, out);
}

// round 7
// speedup vs baseline: 2.9135x; 1.0134x over previous
#include <cuda_runtime.h>
#include <cuda_fp16.h>
#include <cstdint>

#define BATCH 8192
#define OUTF  4096
#define INF   4096
#define PACKED_LEN 512

// ---------------- GEMM tiling ----------------
#define TM 128
#define TN 64
#define KS 128                       // fp8 K elements per stage (128 B rows)
#define NK (INF / KS)                // 32 K-iterations
#define STAGES 3
#define THREADS 256

#define A_TILE_BYTES (TM * 128)          // 16 KB
#define B_TILE_BYTES (TN * 128)          // 8 KB
#define STAGE_BYTES (A_TILE_BYTES + B_TILE_BYTES)  // 24 KB
#define SMEM_DYN (STAGES * STAGE_BYTES + 1024)     // ~73 KB -> 3 CTAs/SM

// Scratch: unpacked +/-1 e4m3 (no cudaMalloc allowed -> __device__ globals)
__device__ __align__(16) uint8_t g_A[(size_t)BATCH * INF];  // 32 MB
__device__ __align__(16) uint8_t g_W[(size_t)OUTF * INF];   // 16 MB

// ---------------- helpers ----------------
__device__ __forceinline__ uint32_t smem_u32(const void* p) {
    return (uint32_t)__cvta_generic_to_shared(p);
}

__device__ __forceinline__ void cp_async16(uint32_t sdst, const void* gsrc) {
    asm volatile("cp.async.cg.shared.global [%0], [%1], 16;" :: "r"(sdst), "l"(gsrc));
}
__device__ __forceinline__ void cp_commit() {
    asm volatile("cp.async.commit_group;");
}
template <int N>
__device__ __forceinline__ void cp_wait() {
    asm volatile("cp.async.wait_group %0;" :: "n"(N));
}

__device__ __forceinline__ void ldsm_x4(uint32_t* r, uint32_t addr) {
    asm volatile("ldmatrix.sync.aligned.m8n8.x4.shared.b16 {%0,%1,%2,%3}, [%4];"
                 : "=r"(r[0]), "=r"(r[1]), "=r"(r[2]), "=r"(r[3]) : "r"(addr));
}

// FP8 e4m3 x e4m3 -> f16 accumulator (exact: acc is always an even int <= 4096)
__device__ __forceinline__ void qmma_f16(uint32_t* c, const uint32_t* a,
                                         uint32_t b0, uint32_t b1) {
    asm volatile(
        "mma.sync.aligned.m16n8k32.row.col.f16.e4m3.e4m3.f16 "
        "{%0,%1}, {%2,%3,%4,%5}, {%6,%7}, {%0,%1};"
        : "+r"(c[0]), "+r"(c[1])
        : "r"(a[0]), "r"(a[1]), "r"(a[2]), "r"(a[3]), "r"(b0), "r"(b1));
}

// ---------------- Unpack: 8 bits (LSB-first) -> 8 e4m3 (+1 / -1) ----------------
__device__ __forceinline__ uint2 unpack8(unsigned v) {
    uint2 r;
    r.x = 0xB8B8B8B8u ^ (((v >> 0) & 1u) << 7)
                      ^ (((v >> 1) & 1u) << 15)
                      ^ (((v >> 2) & 1u) << 23)
                      ^ (((v >> 3) & 1u) << 31);
    r.y = 0xB8B8B8B8u ^ (((v >> 4) & 1u) << 7)
                      ^ (((v >> 5) & 1u) << 15)
                      ^ (((v >> 6) & 1u) << 23)
                      ^ (((v >> 7) & 1u) << 31);
    return r;
}

#define NA2 (BATCH * PACKED_LEN / 2)   // 2097152
#define NW2 (OUTF * PACKED_LEN / 2)    // 1048576
__global__ void unpack_all_kernel(const int* __restrict__ pa,
                                  const int* __restrict__ pw) {
    int i = blockIdx.x * blockDim.x + threadIdx.x;
    const int* src;
    uint4* dst;
    int idx;
    if (i < NA2) { src = pa; dst = (uint4*)g_A; idx = i; }
    else if (i < NA2 + NW2) { src = pw; dst = (uint4*)g_W; idx = i - NA2; }
    else return;
    uint2 lo = unpack8((unsigned)src[2 * idx]);
    uint2 hi = unpack8((unsigned)src[2 * idx + 1]);
    dst[idx] = make_uint4(lo.x, lo.y, hi.x, hi.y);
}

// ---------------- FP8 MMA GEMM: CTA 128x64, 8 warps as 4(M) x 2(N), warp 32x32 ----
// smem: A 128 rows x 128B then B 64 rows x 128B, XOR-swizzled 16B chunks.
__global__ __launch_bounds__(THREADS, 3)
void bitlinear_gemm(const float* __restrict__ bias, float* __restrict__ out) {
    extern __shared__ char smem_raw[];
    char* smem = (char*)(((uintptr_t)smem_raw + 1023) & ~(uintptr_t)1023);
    const uint32_t sbase = smem_u32(smem);

    const int tid  = threadIdx.x;
    const int wid  = tid >> 5;
    const int lane = tid & 31;
    const int warp_m = wid & 3;    // 4 x 32 rows
    const int warp_n = wid >> 2;   // 2 x 32 cols

    const int ntile = blockIdx.x & (OUTF / TN - 1);  // 0..63
    const int mtile = blockIdx.x >> 6;               // 0..63

    const uint8_t* __restrict__ Ag0 = g_A + (size_t)(mtile * TM) * INF;
    const uint8_t* __restrict__ Wg0 = g_W + (size_t)(ntile * TN) * INF;

    // ---- prefetch geometry: 1536 16B-chunks/stage (A:1024, B:512) ----
    const int tr = tid >> 3;    // 0..31
    const int tc = tid & 7;     // 0..7
    const uint8_t* pf_gA = Ag0 + (size_t)tr * INF + tc * 16;
    const uint8_t* pf_gW = Wg0 + (size_t)tr * INF + tc * 16;
    const uint32_t pf_s  = tr * 128 + ((tc ^ (tr & 7)) << 4);

    auto prefetch = [&](int kt) {
        const uint32_t sst = sbase + (kt % STAGES) * STAGE_BYTES;
        const uint8_t* ga = pf_gA + kt * KS;
        const uint8_t* gw = pf_gW + kt * KS;
#pragma unroll
        for (int it = 0; it < 4; ++it)   // A: rows tr, tr+32, tr+64, tr+96
            cp_async16(sst + pf_s + it * (32 * 128), ga + (size_t)it * (32 * INF));
#pragma unroll
        for (int it = 0; it < 2; ++it)   // B: rows tr, tr+32
            cp_async16(sst + A_TILE_BYTES + pf_s + it * (32 * 128),
                       gw + (size_t)it * (32 * INF));
        cp_commit();
    };

    // ---- ldmatrix geometry ----
    const int j = lane >> 3;
    const int arow_in = (lane & 7) + ((j & 1) << 3);
    const int achk    = j >> 1;
    const int brow_in = (lane & 7) + ((j >> 1) << 3);
    const int bchk    = j & 1;

    uint32_t offA[2][4];   // [mf][ks]
    uint32_t offB[2][4];   // [nb][ks]
#pragma unroll
    for (int mf = 0; mf < 2; ++mf) {
        int row = warp_m * 32 + mf * 16 + arow_in;
#pragma unroll
        for (int ks = 0; ks < 4; ++ks)
            offA[mf][ks] = row * 128 + (((ks * 2 + achk) ^ (row & 7)) << 4);
    }
#pragma unroll
    for (int nb = 0; nb < 2; ++nb) {
        int row = warp_n * 32 + nb * 16 + brow_in;
#pragma unroll
        for (int ks = 0; ks < 4; ++ks)
            offB[nb][ks] = A_TILE_BYTES + row * 128 +
                           (((ks * 2 + bchk) ^ (row & 7)) << 4);
    }

    // f16x2 accumulators: [mf][nf] (nf over 4 x n8)
    uint32_t c_acc[2][4][2];
#pragma unroll
    for (int mf = 0; mf < 2; ++mf)
#pragma unroll
        for (int nf = 0; nf < 4; ++nf) {
            c_acc[mf][nf][0] = 0u;
            c_acc[mf][nf][1] = 0u;
        }

    prefetch(0);
    prefetch(1);

    for (int kt = 0; kt < NK; ++kt) {
        cp_wait<STAGES - 2>();
        __syncthreads();

        if (kt + 2 < NK) prefetch(kt + 2);

        const uint32_t sa = sbase + (kt % STAGES) * STAGE_BYTES;

#pragma unroll
        for (int ks = 0; ks < 4; ++ks) {
            uint32_t a[2][4], b[2][4];
#pragma unroll
            for (int mf = 0; mf < 2; ++mf) ldsm_x4(a[mf], sa + offA[mf][ks]);
#pragma unroll
            for (int nb = 0; nb < 2; ++nb) ldsm_x4(b[nb], sa + offB[nb][ks]);
#pragma unroll
            for (int mf = 0; mf < 2; ++mf)
#pragma unroll
                for (int nf = 0; nf < 4; ++nf)
                    qmma_f16(c_acc[mf][nf], a[mf],
                             b[nf >> 1][(nf & 1) * 2],
                             b[nf >> 1][(nf & 1) * 2 + 1]);
        }
        // no trailing barrier: next iteration's top barrier protects stage reuse
    }

    // ---------------- epilogue ----------------
    const int gid = lane >> 2;
    const int tig = lane & 3;
#pragma unroll
    for (int mf = 0; mf < 2; ++mf) {
        int r0 = mtile * TM + warp_m * 32 + mf * 16 + gid;
#pragma unroll
        for (int nf = 0; nf < 4; ++nf) {
            int col = ntile * TN + warp_n * 32 + nf * 8 + 2 * tig;
            float bx = __ldg(bias + col);
            float by = __ldg(bias + col + 1);
            half2 h0 = *(half2*)&c_acc[mf][nf][0];
            half2 h1 = *(half2*)&c_acc[mf][nf][1];
            float2 f0 = __half22float2(h0);
            float2 f1 = __half22float2(h1);
            float2 v0, v1;
            v0.x = f0.x + bx;  v0.y = f0.y + by;
            v1.x = f1.x + bx;  v1.y = f1.y + by;
            *(float2*)(void*)(out + (size_t)r0 * OUTF + col) = v0;
            *(float2*)(void*)(out + (size_t)(r0 + 8) * OUTF + col) = v1;
        }
    }
}

// ---------------- launch ----------------
extern "C" void kernel_launch(void* const* d_in, const int* in_sizes, int n_in,
                              void* d_out, int out_size) {
    const int*   inp  = (const int*)d_in[0];   // [8192, 512] int32 (low 8 bits)
    const int*   wp   = (const int*)d_in[1];   // [4096, 512] int32
    const float* bias = (const float*)d_in[2]; // [4096]
    float*       out  = (float*)d_out;         // [8192, 4096] fp32

    cudaFuncSetAttribute(bitlinear_gemm,
                         cudaFuncAttributeMaxDynamicSharedMemorySize, SMEM_DYN);

    const int nTot = NA2 + NW2;
    unpack_all_kernel<<<(nTot + 255) / 256, 256>>>(inp, wp);

    const int grid = (BATCH / TM) * (OUTF / TN);  // 4096
    bitlinear_gemm<<<grid, THREADS, SMEM_DYN>>>(bias, out);
}